// round 10
// baseline (speedup 1.0000x reference)
#include <cuda_runtime.h>
#include <cuda_bf16.h>

#define B_DIM 64
#define T_DIM 512
#define M_DIM 512
#define PAD_INDEX 1
#define LAMBDA1 0.02f
#define LAMBDA2 0.1f

// Scratch: s_trg[t][m] (1 MB, stays L2-hot for K2) and n_valid[t].
__device__ float g_strg[T_DIM * M_DIM];
__device__ float g_nv[T_DIM];

// =====================================================================
// K1: embedding gathers -> s_trg[t,:], n_valid[t]. One CTA per t.
// 8 warps; warp w handles b = w + 8k, k=0..7. Lane holds 16 floats of
// the 512-wide row as float4 chunks at index (lane + 32c), c=0..3.
// Depth-3 register pipeline, one butterfly per row.
// =====================================================================
__global__ __launch_bounds__(256, 3) void vmf_k1_strg(
    const int*   __restrict__ targets,    // [B,T]
    const float* __restrict__ embedding,  // [V,M]
    float* __restrict__ out)              // zeroed here for K2
{
    const int t    = blockIdx.x;
    const int tid  = threadIdx.x;
    const int w    = tid >> 5;
    const int lane = tid & 31;

    if (t == 0 && tid == 0) out[0] = 0.0f;   // K1 completes before K2 starts

    __shared__ float shf[8 * 512];           // 16 KB combine buffer
    __shared__ float sh_nv[8];
    float4* shv4 = (float4*)shf;

    float acc[16];
#pragma unroll
    for (int i = 0; i < 16; i++) acc[i] = 0.0f;
    float n_valid = 0.0f;                    // lane-uniform

    int tg[8];
#pragma unroll
    for (int k = 0; k < 8; k++)
        tg[k] = __ldg(&targets[(w + 8 * k) * T_DIM + t]);

    float4 buf[3][4];
#pragma unroll
    for (int s = 0; s < 2; s++) {
        const float4* erow = (const float4*)(embedding + (size_t)tg[s] * M_DIM);
#pragma unroll
        for (int c = 0; c < 4; c++) buf[s][c] = __ldg(&erow[lane + 32 * c]);
    }

#pragma unroll
    for (int k = 0; k < 8; k++) {
        if (k + 2 < 8) {
            const float4* erow =
                (const float4*)(embedding + (size_t)tg[k + 2] * M_DIM);
#pragma unroll
            for (int c = 0; c < 4; c++)
                buf[(k + 2) % 3][c] = __ldg(&erow[lane + 32 * c]);
        }
        const float4* e = buf[k % 3];

        float es = 0.0f;
#pragma unroll
        for (int c = 0; c < 4; c++)
            es += e[c].x * e[c].x + e[c].y * e[c].y +
                  e[c].z * e[c].z + e[c].w * e[c].w;
#pragma unroll
        for (int off = 16; off > 0; off >>= 1)
            es += __shfl_xor_sync(0xffffffffu, es, off);

        const float mask  = (tg[k] != PAD_INDEX) ? 1.0f : 0.0f;
        const float inv_e = mask * rsqrtf(fmaxf(es, 1e-24f));
        n_valid += mask;
#pragma unroll
        for (int c = 0; c < 4; c++) {
            acc[c * 4 + 0] += e[c].x * inv_e;
            acc[c * 4 + 1] += e[c].y * inv_e;
            acc[c * 4 + 2] += e[c].z * inv_e;
            acc[c * 4 + 3] += e[c].w * inv_e;
        }
    }

    // combine across warps; thread owns m = tid and m = tid+256
#pragma unroll
    for (int c = 0; c < 4; c++)
        shv4[w * 128 + lane + 32 * c] =
            make_float4(acc[c * 4 + 0], acc[c * 4 + 1],
                        acc[c * 4 + 2], acc[c * 4 + 3]);
    if (lane == 0) sh_nv[w] = n_valid;
    __syncthreads();

    float s0 = 0.0f, s1 = 0.0f;
#pragma unroll
    for (int ww = 0; ww < 8; ww++) {
        s0 += shf[ww * 512 + tid];
        s1 += shf[ww * 512 + tid + 256];
    }
    g_strg[t * M_DIM + tid]       = s0;
    g_strg[t * M_DIM + tid + 256] = s1;

    if (tid == 0) {
        float nv = 0.0f;
#pragma unroll
        for (int i = 0; i < 8; i++) nv += sh_nv[i];
        g_nv[t] = nv;
    }
}

// =====================================================================
// K2: outputs stream. One CTA per t. Lane preloads its 16 floats of
// s_trg[t] (L2-hot); per row only ONE butterfly (ss) — the lane-local
// dot pd needs no reduction until the epilogue:
//   sum_b <o_n[b], s_trg> = sum_lane sum_b inv_o_b * pd[b,lane]
// =====================================================================
__global__ __launch_bounds__(256, 3) void vmf_k2_loss(
    const float* __restrict__ outputs,    // [B,T,M]
    float* __restrict__ out)
{
    const int t    = blockIdx.x;
    const int tid  = threadIdx.x;
    const int w    = tid >> 5;
    const int lane = tid & 31;

    __shared__ float sh_dot[8], sh_a[8];

    // lane's slice of s_trg[t] (16 floats; 1 MB buffer -> L2 hit)
    float4 s4[4];
    {
        const float4* srow = (const float4*)(g_strg + (size_t)t * M_DIM);
#pragma unroll
        for (int c = 0; c < 4; c++) s4[c] = __ldg(&srow[lane + 32 * c]);
    }

    float sum_a  = 0.0f;   // lane-uniform
    float dotacc = 0.0f;   // lane-local

    float4 buf[3][4];
#pragma unroll
    for (int s = 0; s < 2; s++) {
        const float4* orow =
            (const float4*)(outputs + ((size_t)(w + 8 * s) * T_DIM + t) * M_DIM);
#pragma unroll
        for (int c = 0; c < 4; c++) buf[s][c] = __ldg(&orow[lane + 32 * c]);
    }

#pragma unroll
    for (int k = 0; k < 8; k++) {
        if (k + 2 < 8) {
            const float4* orow =
                (const float4*)(outputs +
                                ((size_t)(w + 8 * (k + 2)) * T_DIM + t) * M_DIM);
#pragma unroll
            for (int c = 0; c < 4; c++)
                buf[(k + 2) % 3][c] = __ldg(&orow[lane + 32 * c]);
        }
        const float4* o = buf[k % 3];

        // ss (needs butterfly) and pd (lane-local, overlaps the butterfly)
        float ss = 0.0f, pd = 0.0f;
#pragma unroll
        for (int c = 0; c < 4; c++) {
            ss += o[c].x * o[c].x + o[c].y * o[c].y +
                  o[c].z * o[c].z + o[c].w * o[c].w;
            pd += o[c].x * s4[c].x + o[c].y * s4[c].y +
                  o[c].z * s4[c].z + o[c].w * s4[c].w;
        }
#pragma unroll
        for (int off = 16; off > 0; off >>= 1)
            ss += __shfl_xor_sync(0xffffffffu, ss, off);

        const float inv_o = rsqrtf(fmaxf(ss, 1e-24f));
        dotacc += inv_o * pd;

        // logC_m(kappa), v = M/2-1 = 255:
        //   sqrt(256^2 + z^2) - 254*log(254 + sqrt(254^2 + z^2))
        const float kappa = sqrtf(ss);
        const float logc  = sqrtf(65536.0f + ss)
                          - 254.0f * __logf(254.0f + sqrtf(64516.0f + ss));
        sum_a += (-logc + LAMBDA1 * kappa);
    }

    // reduce dotacc across lanes, then warps
#pragma unroll
    for (int off = 16; off > 0; off >>= 1)
        dotacc += __shfl_xor_sync(0xffffffffu, dotacc, off);

    if (lane == 0) { sh_dot[w] = dotacc; sh_a[w] = sum_a; }
    __syncthreads();

    if (tid == 0) {
        float dot = 0.0f, sa = 0.0f;
#pragma unroll
        for (int i = 0; i < 8; i++) { dot += sh_dot[i]; sa += sh_a[i]; }
        const float val = g_nv[t] * sa - LAMBDA2 * dot;
        atomicAdd(out, val);
    }
}

extern "C" void kernel_launch(void* const* d_in, const int* in_sizes, int n_in,
                              void* d_out, int out_size) {
    const float* outputs   = (const float*)d_in[0];
    const int*   targets   = (const int*)d_in[1];
    const float* embedding = (const float*)d_in[2];
    float* out = (float*)d_out;

    vmf_k1_strg<<<T_DIM, 256>>>(targets, embedding, out);
    vmf_k2_loss<<<T_DIM, 256>>>(outputs, out);
}

// round 11
// speedup vs baseline: 1.3972x; 1.3972x over previous
#include <cuda_runtime.h>
#include <cuda_bf16.h>

#define B_DIM 64
#define T_DIM 512
#define M_DIM 512
#define PAD_INDEX 1
#define LAMBDA1 0.02f
#define LAMBDA2 0.1f

__global__ void zero_out_kernel(float* out) { out[0] = 0.0f; }

// One CTA per t. 256 threads = 8 warps; warp w handles b = w + 8k, k=0..7.
// Each lane holds 16 floats of the 512-wide row: float4 chunks at
// float4-index (lane + 32c), c=0..3  => m = 4*(lane+32c) .. +3.
// Mixed depth-2 software pipeline (outputs + embedding loads in flight
// together — proven fastest structure); tail shortened with MUFU
// transcendentals (__logf, rsqrtf).
__global__ __launch_bounds__(256, 2) void vmf_loss_kernel(
    const float* __restrict__ outputs,    // [B,T,M]  read-once
    const int*   __restrict__ targets,    // [B,T]
    const float* __restrict__ embedding,  // [V,M]    gathered
    float* __restrict__ out)
{
    const int t    = blockIdx.x;
    const int tid  = threadIdx.x;
    const int w    = tid >> 5;
    const int lane = tid & 31;

    float acc_o[16];
    float acc_t[16];
#pragma unroll
    for (int i = 0; i < 16; i++) { acc_o[i] = 0.0f; acc_t[i] = 0.0f; }

    float sum_a   = 0.0f;   // lane-uniform
    float n_valid = 0.0f;   // lane-uniform

    int tg[8];
#pragma unroll
    for (int k = 0; k < 8; k++)
        tg[k] = __ldg(&targets[(w + 8 * k) * T_DIM + t]);

    // ---- prologue: issue loads for iteration 0 ----
    float4 o[4], e[4];
    {
        const float4* orow =
            (const float4*)(outputs + ((size_t)w * T_DIM + t) * M_DIM);
        const float4* erow = (const float4*)(embedding + (size_t)tg[0] * M_DIM);
#pragma unroll
        for (int c = 0; c < 4; c++) o[c] = __ldlu(&orow[lane + 32 * c]);
#pragma unroll
        for (int c = 0; c < 4; c++) e[c] = __ldg(&erow[lane + 32 * c]);
    }

#pragma unroll
    for (int k = 0; k < 8; k++) {
        const int tgt = tg[k];

        // ---- issue NEXT iteration's loads before this iteration's math ----
        float4 on[4], en[4];
        if (k < 7) {
            const int bn = w + 8 * (k + 1);
            const float4* orow =
                (const float4*)(outputs + ((size_t)bn * T_DIM + t) * M_DIM);
            const float4* erow =
                (const float4*)(embedding + (size_t)tg[k + 1] * M_DIM);
#pragma unroll
            for (int c = 0; c < 4; c++) on[c] = __ldlu(&orow[lane + 32 * c]);
#pragma unroll
            for (int c = 0; c < 4; c++) en[c] = __ldg(&erow[lane + 32 * c]);
        }

        // ---- per-lane partial sums of squares for BOTH rows ----
        float ss = 0.0f, es = 0.0f;
#pragma unroll
        for (int c = 0; c < 4; c++) {
            ss += o[c].x * o[c].x + o[c].y * o[c].y +
                  o[c].z * o[c].z + o[c].w * o[c].w;
            es += e[c].x * e[c].x + e[c].y * e[c].y +
                  e[c].z * e[c].z + e[c].w * e[c].w;
        }

        // ---- interleaved butterfly reductions (independent chains) ----
#pragma unroll
        for (int off = 16; off > 0; off >>= 1) {
            ss += __shfl_xor_sync(0xffffffffu, ss, off);
            es += __shfl_xor_sync(0xffffffffu, es, off);
        }

        // ---- short MUFU-based tail ----
        const float inv_o = rsqrtf(fmaxf(ss, 1e-24f));
        const float mask  = (tgt != PAD_INDEX) ? 1.0f : 0.0f;
        const float inv_e = mask * rsqrtf(fmaxf(es, 1e-24f));
        n_valid += mask;

#pragma unroll
        for (int c = 0; c < 4; c++) {
            acc_o[c * 4 + 0] += o[c].x * inv_o;
            acc_o[c * 4 + 1] += o[c].y * inv_o;
            acc_o[c * 4 + 2] += o[c].z * inv_o;
            acc_o[c * 4 + 3] += o[c].w * inv_o;
            acc_t[c * 4 + 0] += e[c].x * inv_e;
            acc_t[c * 4 + 1] += e[c].y * inv_e;
            acc_t[c * 4 + 2] += e[c].z * inv_e;
            acc_t[c * 4 + 3] += e[c].w * inv_e;
        }

        // logC_m(kappa), v = M/2-1 = 255:
        //   sqrt(256^2 + z^2) - 254*log(254 + sqrt(254^2 + z^2))
        const float kappa = sqrtf(ss);
        const float logc  = sqrtf(65536.0f + ss)
                          - 254.0f * __logf(254.0f + sqrtf(64516.0f + ss));
        sum_a += (-logc + LAMBDA1 * kappa);

        // rotate pipeline registers (renamed away by unroll)
#pragma unroll
        for (int c = 0; c < 4; c++) { o[c] = on[c]; e[c] = en[c]; }
    }

    // ---- block combine: s_out[m], s_trg[m], dot ----
    __shared__ float4 shv[8 * 128];   // 16 KB, reused for both passes
    __shared__ float  sh_dot[8];
    __shared__ float  sh_a[8];
    __shared__ float  sh_nv[8];

    float* shf = (float*)shv;   // [warp][512] floats

    // pass A: s_out
#pragma unroll
    for (int c = 0; c < 4; c++)
        shv[w * 128 + lane + 32 * c] =
            make_float4(acc_o[c * 4 + 0], acc_o[c * 4 + 1],
                        acc_o[c * 4 + 2], acc_o[c * 4 + 3]);
    __syncthreads();

    // thread owns m = tid and m = tid + 256
    float so0 = 0.0f, so1 = 0.0f;
#pragma unroll
    for (int ww = 0; ww < 8; ww++) {
        so0 += shf[ww * 512 + tid];
        so1 += shf[ww * 512 + tid + 256];
    }
    __syncthreads();

    // pass B: s_trg
#pragma unroll
    for (int c = 0; c < 4; c++)
        shv[w * 128 + lane + 32 * c] =
            make_float4(acc_t[c * 4 + 0], acc_t[c * 4 + 1],
                        acc_t[c * 4 + 2], acc_t[c * 4 + 3]);
    __syncthreads();

    float st0 = 0.0f, st1 = 0.0f;
#pragma unroll
    for (int ww = 0; ww < 8; ww++) {
        st0 += shf[ww * 512 + tid];
        st1 += shf[ww * 512 + tid + 256];
    }

    float dp = so0 * st0 + so1 * st1;
#pragma unroll
    for (int off = 16; off > 0; off >>= 1)
        dp += __shfl_xor_sync(0xffffffffu, dp, off);

    if (lane == 0) {
        sh_dot[w] = dp;
        sh_a[w]   = sum_a;
        sh_nv[w]  = n_valid;
    }
    __syncthreads();

    if (tid == 0) {
        float dot = 0.0f, sa = 0.0f, nv = 0.0f;
#pragma unroll
        for (int i = 0; i < 8; i++) {
            dot += sh_dot[i];
            sa  += sh_a[i];
            nv  += sh_nv[i];
        }
        const float val = nv * sa - LAMBDA2 * dot;
        atomicAdd(out, val);
    }
}

extern "C" void kernel_launch(void* const* d_in, const int* in_sizes, int n_in,
                              void* d_out, int out_size) {
    const float* outputs   = (const float*)d_in[0];
    const int*   targets   = (const int*)d_in[1];
    const float* embedding = (const float*)d_in[2];
    float* out = (float*)d_out;

    zero_out_kernel<<<1, 1>>>(out);
    vmf_loss_kernel<<<T_DIM, 256>>>(outputs, targets, embedding, out);
}